// round 3
// baseline (speedup 1.0000x reference)
#include <cuda_runtime.h>
#include <cstdint>
#include <cstddef>

#define LSEQ 2048
#define NH 8
#define DK 128
#define DV 128
#define CH 3072          // 2*KEY_DIM + VALUE_DIM = 2*1024 + 1024
#define LPB 16           // scan steps per cp.async block
#define NB (LSEQ / LPB)  // 128 blocks

// ---------------- scratch (no allocations allowed) ----------------
// 256B-aligned: cp.async 16B variant requires 16B-aligned global srcs.
__device__ __align__(256) float g_qs[NH * LSEQ * DK];   // normalized q * DK^-0.5, [h][l][d]
__device__ __align__(256) float g_ks[NH * LSEQ * DK];   // normalized k,           [h][l][d]
__device__ __align__(256) float g_vs[NH * LSEQ * DV];   // v,                      [h][l][d]
__device__ __align__(256) float g_sc[NH * LSEQ * 2];    // {exp(g), beta},         [h][l][2]

typedef unsigned long long u64;

// ---------------- packed f32x2 helpers (sm_100+ FFMA2 path) ----------------
__device__ __forceinline__ u64 pk2(float x, float y) {
    u64 r; asm("mov.b64 %0, {%1, %2};" : "=l"(r) : "f"(x), "f"(y)); return r;
}
__device__ __forceinline__ u64 fma2(u64 a, u64 b, u64 c) {
    u64 d; asm("fma.rn.f32x2 %0, %1, %2, %3;" : "=l"(d) : "l"(a), "l"(b), "l"(c)); return d;
}
__device__ __forceinline__ u64 mul2(u64 a, u64 b) {
    u64 d; asm("mul.rn.f32x2 %0, %1, %2;" : "=l"(d) : "l"(a), "l"(b)); return d;
}
__device__ __forceinline__ u64 add2(u64 a, u64 b) {
    u64 d; asm("add.rn.f32x2 %0, %1, %2;" : "=l"(d) : "l"(a), "l"(b)); return d;
}
__device__ __forceinline__ float2 up2(u64 a) {
    float lo, hi; asm("mov.b64 {%0, %1}, %2;" : "=f"(lo), "=f"(hi) : "l"(a));
    return make_float2(lo, hi);
}
__device__ __forceinline__ void cp16(uint32_t dst, const void* src) {
    asm volatile("cp.async.cg.shared.global [%0], [%1], 16;" :: "r"(dst), "l"(src) : "memory");
}

// =====================================================================
// Kernel 1: causal depthwise conv(K=4) + SiLU, split q/k/v, l2norm q/k,
//           gating -> exp(g), beta.   One CTA per sequence position l.
// =====================================================================
__global__ void __launch_bounds__(256) prep_kernel(
    const float* __restrict__ x,       // [L, 3072]
    const float* __restrict__ agate,   // [L, 8]
    const float* __restrict__ bgate,   // [L, 8]
    const float* __restrict__ A_log,   // [8]
    const float* __restrict__ dtb,     // [8]
    const float* __restrict__ w,       // [3072, 4]
    const float* __restrict__ cbias)   // [3072]
{
    __shared__ __align__(16) float y[CH];
    const int l = blockIdx.x;
    const int tid = threadIdx.x;

    // conv + SiLU
    for (int c = tid; c < CH; c += 256) {
        float4 wc = ((const float4*)w)[c];
        float s = cbias[c];
        if (l >= 3) {
            s += x[(size_t)(l - 3) * CH + c] * wc.x;
            s += x[(size_t)(l - 2) * CH + c] * wc.y;
            s += x[(size_t)(l - 1) * CH + c] * wc.z;
            s += x[(size_t)(l    ) * CH + c] * wc.w;
        } else {
            if (l - 3 >= 0) s += x[(size_t)(l - 3) * CH + c] * wc.x;
            if (l - 2 >= 0) s += x[(size_t)(l - 2) * CH + c] * wc.y;
            if (l - 1 >= 0) s += x[(size_t)(l - 1) * CH + c] * wc.z;
            s += x[(size_t)l * CH + c] * wc.w;
        }
        float sig = 1.0f / (1.0f + expf(-s));
        y[c] = s * sig;
    }
    __syncthreads();

    const int wid = tid >> 5, lane = tid & 31;
    // 16 l2norm groups (8 q heads, 8 k heads), 2 per warp
    for (int g = wid; g < 16; g += 8) {
        const int isQ = (g < 8);
        const int h = g & 7;
        const float4 yv = *(const float4*)&y[(isQ ? 0 : 1024) + h * DK + lane * 4];
        float ss = yv.x * yv.x + yv.y * yv.y + yv.z * yv.z + yv.w * yv.w;
        #pragma unroll
        for (int o = 16; o >= 1; o >>= 1) ss += __shfl_xor_sync(0xffffffffu, ss, o);
        float scale = rsqrtf(ss + 1e-6f);
        if (isQ) scale *= 0.08838834764831845f;   // DK^-0.5
        float* dst = (isQ ? g_qs : g_ks) + ((size_t)h * LSEQ + l) * DK + lane * 4;
        *(float4*)dst = make_float4(yv.x * scale, yv.y * scale, yv.z * scale, yv.w * scale);
    }
    // v passthrough (transpose to [h][l][d])
    for (int i = tid; i < NH * DV; i += 256) {
        const int h = i >> 7, d = i & 127;
        g_vs[((size_t)h * LSEQ + l) * DV + d] = y[2048 + i];
    }
    // gating
    if (tid < NH) {
        const int h = tid;
        float xg = agate[l * NH + h] + dtb[h];
        float sp = (xg > 20.0f) ? xg : log1pf(expf(xg));
        float gg = -expf(A_log[h]) * sp;
        float bb = bgate[l * NH + h];
        g_sc[((size_t)h * LSEQ + l) * 2 + 0] = expf(gg);
        g_sc[((size_t)h * LSEQ + l) * 2 + 1] = 1.0f / (1.0f + expf(-bb));
    }
}

// =====================================================================
// Kernel 2: gated delta-rule scan. 128 CTAs x 32 threads.
// CTA = (head h, column-group grp): 8 DV columns. 4 lanes/column,
// each lane owns 32 dk rows of S for its column (registers).
//
// SMEM layout: each step's 128-float k (and q) vector is stored as
// 32 16B chunks PERMUTED: chunk c lives at position (c&7)*4 + (c>>3).
// Lane (cg, j) reads positions i*4 + j (i = 0..7) -> byte addr
// i*64 + j*16: the 4 distinct j-lines per LDS.128 phase hit 16 distinct
// banks (conflict-free). Lane j therefore holds original chunks
// c = j*8 + i, i.e. dk rows [j*32, j*32+32) — contiguous, matching S2.
// =====================================================================
template<bool PF>
__device__ __forceinline__ void scan_step(
    int t, int koff, int voff, int scoff, int pfoff,
    ulonglong2 (&K)[8], ulonglong2 (&KN)[8], u64 (&S2)[16],
    const ulonglong2* __restrict__ sK2, const ulonglong2* __restrict__ sQ2,
    const float* __restrict__ sVf, const float* __restrict__ sSCf,
    int j, int cg, int h, int col, float* __restrict__ out)
{
    const float egt = sSCf[scoff + 0];
    const float bet = sSCf[scoff + 1];
    const float v   = sVf[voff + cg];

    if (PF) {   // prefetch next step's k into the alternate register buffer
        #pragma unroll
        for (int i = 0; i < 8; i++) KN[i] = sK2[pfoff + i * 4 + j];
    }

    // acc = k . S_old   (this lane's 32-row slice)
    u64 a0 = 0, a1 = 0, a2 = 0, a3 = 0;
    #pragma unroll
    for (int i = 0; i < 4; i++) {
        a0 = fma2(K[i].x, S2[2 * i],     a0);
        a1 = fma2(K[i].y, S2[2 * i + 1], a1);
    }
    #pragma unroll
    for (int i = 4; i < 8; i++) {
        a2 = fma2(K[i].x, S2[2 * i],     a2);
        a3 = fma2(K[i].y, S2[2 * i + 1], a3);
    }
    float2 f = up2(add2(add2(a0, a2), add2(a1, a3)));
    float acc = f.x + f.y;
    acc += __shfl_xor_sync(0xffffffffu, acc, 1);
    acc += __shfl_xor_sync(0xffffffffu, acc, 2);

    // err = v - k.(eg*S_old) = v - eg*(k.S_old)
    const float err  = v - egt * acc;
    const float berr = bet * err;
    const u64 eg2 = pk2(egt, egt);
    const u64 be2 = pk2(berr, berr);

    // S_new = eg*S_old + k*berr ;  o = q . S_new
    u64 o0 = 0, o1 = 0, o2 = 0, o3 = 0;
    #pragma unroll
    for (int i = 0; i < 4; i++) {
        ulonglong2 q = sQ2[koff + i * 4 + j];
        u64 tx = mul2(K[i].x, be2);
        S2[2 * i] = fma2(eg2, S2[2 * i], tx);
        o0 = fma2(q.x, S2[2 * i], o0);
        u64 ty = mul2(K[i].y, be2);
        S2[2 * i + 1] = fma2(eg2, S2[2 * i + 1], ty);
        o1 = fma2(q.y, S2[2 * i + 1], o1);
    }
    #pragma unroll
    for (int i = 4; i < 8; i++) {
        ulonglong2 q = sQ2[koff + i * 4 + j];
        u64 tx = mul2(K[i].x, be2);
        S2[2 * i] = fma2(eg2, S2[2 * i], tx);
        o2 = fma2(q.x, S2[2 * i], o2);
        u64 ty = mul2(K[i].y, be2);
        S2[2 * i + 1] = fma2(eg2, S2[2 * i + 1], ty);
        o3 = fma2(q.y, S2[2 * i + 1], o3);
    }
    float2 fo = up2(add2(add2(o0, o2), add2(o1, o3)));
    float oacc = fo.x + fo.y;
    oacc += __shfl_xor_sync(0xffffffffu, oacc, 1);
    oacc += __shfl_xor_sync(0xffffffffu, oacc, 2);
    if (j == 0) out[((size_t)t * NH + h) * DV + col] = oacc;
}

__global__ void __launch_bounds__(32, 1) scan_kernel(float* __restrict__ out)
{
    __shared__ __align__(16) float4 sK[2 * LPB * 32];   // 16 KB
    __shared__ __align__(16) float4 sQ[2 * LPB * 32];   // 16 KB
    __shared__ __align__(16) float  sV[2 * LPB * 8];    // 1 KB
    __shared__ __align__(16) float  sSC[2 * LPB * 2];   // 256 B

    const int bx   = blockIdx.x;
    const int h    = bx >> 4;
    const int grp  = bx & 15;
    const int lane = threadIdx.x;
    const int cg   = lane >> 2;      // column within group (0..7)
    const int j    = lane & 3;       // 32-row slice index
    const int col  = grp * 8 + cg;
    const int perm = ((lane & 7) << 2) | (lane >> 3);   // conflict-free chunk position

    const float* kh  = g_ks + (size_t)h * LSEQ * DK;
    const float* qh  = g_qs + (size_t)h * LSEQ * DK;
    const float* vh  = g_vs + (size_t)h * LSEQ * DV;
    const float* sch = g_sc + (size_t)h * LSEQ * 2;

    const uint32_t sK_a  = (uint32_t)__cvta_generic_to_shared(sK);
    const uint32_t sQ_a  = (uint32_t)__cvta_generic_to_shared(sQ);
    const uint32_t sV_a  = (uint32_t)__cvta_generic_to_shared(sV);
    const uint32_t sSC_a = (uint32_t)__cvta_generic_to_shared(sSC);

    auto issue = [&](int n, int buf) {
        const float4* gk = (const float4*)kh + (size_t)n * LPB * 32;
        const float4* gq = (const float4*)qh + (size_t)n * LPB * 32;
        const uint32_t dk_ = sK_a + (uint32_t)(buf * 512 + perm) * 16u;
        const uint32_t dq_ = sQ_a + (uint32_t)(buf * 512 + perm) * 16u;
        #pragma unroll
        for (int i = 0; i < 16; i++) {
            cp16(dk_ + (uint32_t)i * 32u * 16u, gk + lane + i * 32);
            cp16(dq_ + (uint32_t)i * 32u * 16u, gq + lane + i * 32);
        }
        {   // v: 16 steps x 8 cols -> 32 chunks of 16B
            const int t = lane >> 1, hf = lane & 1;
            const void* src = vh + (size_t)(n * LPB + t) * DV + grp * 8 + hf * 4;
            cp16(sV_a + (uint32_t)(buf * 128 + t * 8 + hf * 4) * 4u, src);
        }
        if (lane < 8) {   // {eg,beta}: 32 floats -> 8 chunks
            const void* src = sch + n * LPB * 2 + lane * 4;
            cp16(sSC_a + (uint32_t)(buf * 32 + lane * 4) * 4u, src);
        }
        asm volatile("cp.async.commit_group;" ::: "memory");
    };

    u64 S2[16];
    #pragma unroll
    for (int i = 0; i < 16; i++) S2[i] = 0ull;
    ulonglong2 kA[8], kB[8];

    issue(0, 0);
    issue(1, 1);
    asm volatile("cp.async.wait_group 1;" ::: "memory");
    __syncthreads();

    const ulonglong2* sK2 = (const ulonglong2*)sK;
    const ulonglong2* sQ2 = (const ulonglong2*)sQ;
    #pragma unroll
    for (int i = 0; i < 8; i++) kA[i] = sK2[i * 4 + j];

    for (int b = 0; b < NB; b++) {
        const int bo  = (b & 1) * 512;      // ull2 offset of buffer
        const int vbo = (b & 1) * LPB * 8;
        const int sco = (b & 1) * LPB * 2;
        const int t0  = b * LPB;

        #pragma unroll 1
        for (int ts2 = 0; ts2 < LPB - 2; ts2 += 2) {
            scan_step<true>(t0 + ts2,     bo + ts2 * 32,       vbo + ts2 * 8,       sco + ts2 * 2,
                            bo + (ts2 + 1) * 32, kA, kB, S2, sK2, sQ2, sV, sSC, j, cg, h, col, out);
            scan_step<true>(t0 + ts2 + 1, bo + (ts2 + 1) * 32, vbo + (ts2 + 1) * 8, sco + (ts2 + 1) * 2,
                            bo + (ts2 + 2) * 32, kB, kA, S2, sK2, sQ2, sV, sSC, j, cg, h, col, out);
        }
        // last pair of the block: second step does no prefetch (next buffer not ready yet)
        scan_step<true >(t0 + LPB - 2, bo + (LPB - 2) * 32, vbo + (LPB - 2) * 8, sco + (LPB - 2) * 2,
                         bo + (LPB - 1) * 32, kA, kB, S2, sK2, sQ2, sV, sSC, j, cg, h, col, out);
        scan_step<false>(t0 + LPB - 1, bo + (LPB - 1) * 32, vbo + (LPB - 1) * 8, sco + (LPB - 1) * 2,
                         0, kB, kA, S2, sK2, sQ2, sV, sSC, j, cg, h, col, out);

        if (b + 2 < NB) issue(b + 2, b & 1);
        else            asm volatile("cp.async.commit_group;" ::: "memory");
        asm volatile("cp.async.wait_group 1;" ::: "memory");
        __syncthreads();
        if (b + 1 < NB) {
            const int nbo = ((b + 1) & 1) * 512;
            #pragma unroll
            for (int i = 0; i < 8; i++) kA[i] = sK2[nbo + i * 4 + j];
        }
    }
}

extern "C" void kernel_launch(void* const* d_in, const int* in_sizes, int n_in,
                              void* d_out, int out_size)
{
    (void)in_sizes; (void)n_in; (void)out_size;
    const float* x      = (const float*)d_in[0];
    const float* agate  = (const float*)d_in[1];
    const float* bgate  = (const float*)d_in[2];
    const float* A_log  = (const float*)d_in[3];
    const float* dtbias = (const float*)d_in[4];
    const float* w      = (const float*)d_in[5];
    const float* cbias  = (const float*)d_in[6];

    prep_kernel<<<LSEQ, 256>>>(x, agate, bgate, A_log, dtbias, w, cbias);
    scan_kernel<<<NH * 16, 32>>>((float*)d_out);
}

// round 11
// speedup vs baseline: 1.4442x; 1.4442x over previous
#include <cuda_runtime.h>
#include <cstdint>
#include <cstddef>

#define LSEQ 2048
#define NH 8
#define DK 128
#define DV 128
#define CH 3072          // 2*KEY_DIM + VALUE_DIM
#define T 16             // chunk length
#define NC (LSEQ / T)    // 128 chunks

// ---------------- scratch (no allocations allowed) ----------------
__device__ __align__(256) float g_qs[NH * LSEQ * DK];   // normalized q * DK^-0.5, [h][l][d]
__device__ __align__(256) float g_ks[NH * LSEQ * DK];   // normalized k,           [h][l][d]
__device__ __align__(256) float g_vs[NH * LSEQ * DV];   // v,                      [h][l][d]
__device__ __align__(256) float g_sc[NH * LSEQ * 2];    // {g (log-decay), beta},  [h][l][2]
__device__ __align__(256) float g_A[NH * NC * T * T];   // A transposed: At[s][u] = exp(gc[u]-gc[s+1])*k_u.k_s (u>s), else 0
__device__ __align__(256) float g_B[NH * NC * T * T];   // B[t][s] = exp(gc[t+1]-gc[s+1])*q_t.k_s (s<=t), else 0
__device__ __align__(256) float g_V[NH * NC * 80];      // per chunk: Dp[16],Df[16],C[16],be[16],beta[16]

typedef unsigned long long u64;

// ---------------- packed f32x2 helpers ----------------
__device__ __forceinline__ u64 pk2(float x, float y) {
    u64 r; asm("mov.b64 %0, {%1, %2};" : "=l"(r) : "f"(x), "f"(y)); return r;
}
__device__ __forceinline__ u64 fma2(u64 a, u64 b, u64 c) {
    u64 d; asm("fma.rn.f32x2 %0, %1, %2, %3;" : "=l"(d) : "l"(a), "l"(b), "l"(c)); return d;
}
__device__ __forceinline__ u64 mul2(u64 a, u64 b) {
    u64 d; asm("mul.rn.f32x2 %0, %1, %2;" : "=l"(d) : "l"(a), "l"(b)); return d;
}
__device__ __forceinline__ float2 up2(u64 a) {
    float lo, hi; asm("mov.b64 {%0, %1}, %2;" : "=f"(lo), "=f"(hi) : "l"(a));
    return make_float2(lo, hi);
}
__device__ __forceinline__ void cp16(uint32_t dst, const void* src) {
    asm volatile("cp.async.cg.shared.global [%0], [%1], 16;" :: "r"(dst), "l"(src) : "memory");
}

// =====================================================================
// Kernel 1: causal depthwise conv(K=4) + SiLU, split q/k/v, l2norm q/k,
//           gating -> store RAW g (log domain) + beta.
// =====================================================================
__global__ void __launch_bounds__(256) prep_kernel(
    const float* __restrict__ x,
    const float* __restrict__ agate,
    const float* __restrict__ bgate,
    const float* __restrict__ A_log,
    const float* __restrict__ dtb,
    const float* __restrict__ w,
    const float* __restrict__ cbias)
{
    __shared__ __align__(16) float y[CH];
    const int l = blockIdx.x;
    const int tid = threadIdx.x;

    for (int c = tid; c < CH; c += 256) {
        float4 wc = ((const float4*)w)[c];
        float s = cbias[c];
        if (l >= 3) {
            s += x[(size_t)(l - 3) * CH + c] * wc.x;
            s += x[(size_t)(l - 2) * CH + c] * wc.y;
            s += x[(size_t)(l - 1) * CH + c] * wc.z;
            s += x[(size_t)(l    ) * CH + c] * wc.w;
        } else {
            if (l - 3 >= 0) s += x[(size_t)(l - 3) * CH + c] * wc.x;
            if (l - 2 >= 0) s += x[(size_t)(l - 2) * CH + c] * wc.y;
            if (l - 1 >= 0) s += x[(size_t)(l - 1) * CH + c] * wc.z;
            s += x[(size_t)l * CH + c] * wc.w;
        }
        float sig = 1.0f / (1.0f + expf(-s));
        y[c] = s * sig;
    }
    __syncthreads();

    const int wid = tid >> 5, lane = tid & 31;
    for (int g = wid; g < 16; g += 8) {
        const int isQ = (g < 8);
        const int h = g & 7;
        const float4 yv = *(const float4*)&y[(isQ ? 0 : 1024) + h * DK + lane * 4];
        float ss = yv.x * yv.x + yv.y * yv.y + yv.z * yv.z + yv.w * yv.w;
        #pragma unroll
        for (int o = 16; o >= 1; o >>= 1) ss += __shfl_xor_sync(0xffffffffu, ss, o);
        float scale = rsqrtf(ss + 1e-6f);
        if (isQ) scale *= 0.08838834764831845f;   // DK^-0.5
        float* dst = (isQ ? g_qs : g_ks) + ((size_t)h * LSEQ + l) * DK + lane * 4;
        *(float4*)dst = make_float4(yv.x * scale, yv.y * scale, yv.z * scale, yv.w * scale);
    }
    for (int i = tid; i < NH * DV; i += 256) {
        const int h = i >> 7, d = i & 127;
        g_vs[((size_t)h * LSEQ + l) * DV + d] = y[2048 + i];
    }
    if (tid < NH) {
        const int h = tid;
        float xg = agate[l * NH + h] + dtb[h];
        float sp = (xg > 20.0f) ? xg : log1pf(expf(xg));
        float gg = -expf(A_log[h]) * sp;          // g <= 0
        float bb = bgate[l * NH + h];
        g_sc[((size_t)h * LSEQ + l) * 2 + 0] = gg;                       // raw log-decay
        g_sc[((size_t)h * LSEQ + l) * 2 + 1] = 1.0f / (1.0f + expf(-bb)); // beta
    }
}

// =====================================================================
// Kernel 2: Gram precompute per (head, chunk). 1024 CTAs x 256 threads.
// Thread (u, s) = (tid>>4, tid&15) computes one A entry and one B entry.
// KSTR=133 keeps the s-indexed shared reads conflict-free (gcd(5,32)=1).
// =====================================================================
#define KSTR 133
__global__ void __launch_bounds__(256) gram_kernel()
{
    __shared__ float sk[T * KSTR];
    __shared__ float sq[T * KSTR];
    __shared__ float sg[T], sb[T], sgc[T + 1];

    const int hc = blockIdx.x;
    const int h = hc >> 7, c = hc & 127;
    const int tid = threadIdx.x;

    const float* kb = g_ks + ((size_t)h * LSEQ + c * T) * DK;
    const float* qb = g_qs + ((size_t)h * LSEQ + c * T) * DK;

    for (int i = tid; i < T * DK; i += 256) {
        int t = i >> 7, u = i & 127;
        sk[t * KSTR + u] = kb[i];
        sq[t * KSTR + u] = qb[i];
    }
    if (tid < T) {
        sg[tid] = g_sc[((size_t)h * LSEQ + c * T + tid) * 2 + 0];
        sb[tid] = g_sc[((size_t)h * LSEQ + c * T + tid) * 2 + 1];
    }
    __syncthreads();
    if (tid == 0) {
        sgc[0] = 0.f;
        #pragma unroll
        for (int t = 0; t < T; t++) sgc[t + 1] = sgc[t] + sg[t];
    }
    __syncthreads();

    const int u = tid >> 4, s = tid & 15;

    // A[u][s] (u>s): exp(gc_u - gc_{s+1}) * k_u.k_s; stored TRANSPOSED at [s][u]
    float a = 0.f;
    if (u > s) {
        float dot = 0.f;
        #pragma unroll 8
        for (int e = 0; e < DK; e++) dot += sk[u * KSTR + e] * sk[s * KSTR + e];
        a = dot * expf(sgc[u] - sgc[s + 1]);
    }
    g_A[(size_t)hc * 256 + s * 16 + u] = a;

    // B[u][s] (s<=u): exp(gc_{u+1} - gc_{s+1}) * q_u.k_s; stored row-major [u][s]
    float bq = 0.f;
    if (s <= u) {
        float dot = 0.f;
        #pragma unroll 8
        for (int e = 0; e < DK; e++) dot += sq[u * KSTR + e] * sk[s * KSTR + e];
        bq = dot * expf(sgc[u + 1] - sgc[s + 1]);
    }
    g_B[(size_t)hc * 256 + u * 16 + s] = bq;

    if (tid < T) {
        const int t = tid;
        float* v = g_V + (size_t)hc * 80;
        v[t]      = expf(sgc[t]);                 // Dp_t = exp(gc_t exclusive)
        v[16 + t] = expf(sgc[t + 1]);             // Df_t = exp(gc_t inclusive)
        v[32 + t] = expf(sgc[T] - sgc[t + 1]);    // C_t
        v[48 + t] = sb[t] * expf(sg[t]);          // be_t = beta_t * exp(g_t)
        v[64 + t] = sb[t];                        // beta_t
    }
}

// =====================================================================
// Kernel 3: chunked scan. 128 CTAs x 128 threads (4 warps).
// CTA = (head, group of 8 DV columns). Thread (cg=tid>>4, rb=tid&15)
// owns rows [rb*8, rb*8+8) of state column (grp*8+cg) in registers.
// Serial chain per step is now ~2 scalar FMAs (no shuffles); heavy work
// (d/dq dots, rank-16 state update, outputs) is warp-parallel.
// =====================================================================
__global__ void __launch_bounds__(128, 1) scan_kernel(float* __restrict__ out)
{
    __shared__ __align__(16) float sK[2][T * DK];   // 16 KB
    __shared__ __align__(16) float sQ[2][T * DK];   // 16 KB
    __shared__ __align__(16) float sA[2][T * 16];   // 2 KB   (At rows: broadcast reads)
    __shared__ __align__(16) float sB[2][T * 20];   // 2.5 KB (padded rows, float4-aligned)
    __shared__ __align__(16) float sV[2][T * 8];    // 1 KB
    __shared__ __align__(16) float sW[2][80];       // 640 B

    const int bx  = blockIdx.x;
    const int h   = bx >> 4;
    const int grp = bx & 15;
    const int tid = threadIdx.x;
    const int cg  = tid >> 4;        // column within group (0..7)
    const int rb  = tid & 15;        // row-block (8 rows each)
    const int col = grp * 8 + cg;

    const float* kb = g_ks + (size_t)h * LSEQ * DK;
    const float* qb = g_qs + (size_t)h * LSEQ * DK;
    const float* vb = g_vs + (size_t)h * LSEQ * DV;

    const uint32_t aK = (uint32_t)__cvta_generic_to_shared(sK);
    const uint32_t aQ = (uint32_t)__cvta_generic_to_shared(sQ);
    const uint32_t aA = (uint32_t)__cvta_generic_to_shared(sA);
    const uint32_t aB = (uint32_t)__cvta_generic_to_shared(sB);
    const uint32_t aV = (uint32_t)__cvta_generic_to_shared(sV);
    const uint32_t aW = (uint32_t)__cvta_generic_to_shared(sW);

    auto issue = [&](int c, int buf) {
        const size_t hc = (size_t)(h * NC + c);
        const float4* gk = (const float4*)(kb + (size_t)c * T * DK);
        const float4* gq = (const float4*)(qb + (size_t)c * T * DK);
        #pragma unroll
        for (int i = 0; i < 4; i++) {
            cp16(aK + (uint32_t)(buf * T * DK + (tid + i * 128) * 4) * 4u, gk + tid + i * 128);
            cp16(aQ + (uint32_t)(buf * T * DK + (tid + i * 128) * 4) * 4u, gq + tid + i * 128);
        }
        if (tid < 64) {            // A: 64 float4
            cp16(aA + (uint32_t)(buf * 256 + tid * 4) * 4u, g_A + hc * 256 + tid * 4);
        } else {                   // B: 64 float4 into padded rows (20 floats)
            int j = tid - 64, r = j >> 2, seg = j & 3;
            cp16(aB + (uint32_t)(buf * 320 + r * 20 + seg * 4) * 4u,
                 g_B + hc * 256 + r * 16 + seg * 4);
        }
        if (tid < 32) {            // v slice: 16 steps x 8 cols
            int t = tid >> 1, half = tid & 1;
            cp16(aV + (uint32_t)(buf * 128 + t * 8 + half * 4) * 4u,
                 vb + (size_t)(c * T + t) * DV + grp * 8 + half * 4);
        } else if (tid < 52) {     // vec: 20 float4
            int j = tid - 32;
            cp16(aW + (uint32_t)(buf * 80 + j * 4) * 4u, g_V + hc * 80 + j * 4);
        }
        asm volatile("cp.async.commit_group;" ::: "memory");
    };

    u64 S2[4] = {0ull, 0ull, 0ull, 0ull};   // 8 state rows (packed pairs)

    issue(0, 0);
    issue(1, 1);
    asm volatile("cp.async.wait_group 1;" ::: "memory");
    __syncthreads();

    for (int c = 0; c < NC; c++) {
        const int buf = c & 1;
        const float* K_ = sK[buf];
        const float* Q_ = sQ[buf];
        const float* A_ = sA[buf];
        const float* B_ = sB[buf];
        const float* V_ = sV[buf];
        const float* W_ = sW[buf];

        // ---- d_t = k_t . S_init, dq_t = q_t . S_init (butterfly over 16 lanes) ----
        float d[T];
        float mydq = 0.f;
        #pragma unroll
        for (int t = 0; t < T; t++) {
            const float4* kp = (const float4*)(K_ + t * DK + rb * 8);
            float4 k0 = kp[0], k1 = kp[1];
            u64 p = fma2(pk2(k0.x, k0.y), S2[0],
                    fma2(pk2(k0.z, k0.w), S2[1],
                    fma2(pk2(k1.x, k1.y), S2[2],
                    mul2(pk2(k1.z, k1.w), S2[3]))));
            float2 pp = up2(p);
            float dt = pp.x + pp.y;

            const float4* qp = (const float4*)(Q_ + t * DK + rb * 8);
            float4 q0 = qp[0], q1 = qp[1];
            u64 pq = fma2(pk2(q0.x, q0.y), S2[0],
                     fma2(pk2(q0.z, q0.w), S2[1],
                     fma2(pk2(q1.x, q1.y), S2[2],
                     mul2(pk2(q1.z, q1.w), S2[3]))));
            float2 qq = up2(pq);
            float dqt = qq.x + qq.y;

            #pragma unroll
            for (int o = 1; o < 16; o <<= 1) {
                dt  += __shfl_xor_sync(0xffffffffu, dt,  o);
                dqt += __shfl_xor_sync(0xffffffffu, dqt, o);
            }
            d[t] = dt;
            if (t == rb) mydq = dqt;    // avoid dynamic register-array index
        }

        // ---- scalar recurrence (redundant on all 16 lanes of the column) ----
        float acc[T], berr[T];
        #pragma unroll
        for (int t = 0; t < T; t++) acc[t] = W_[t] * d[t];     // Dp_t * d_t
        #pragma unroll
        for (int t = 0; t < T; t++) {
            berr[t] = W_[64 + t] * V_[t * 8 + cg] - W_[48 + t] * acc[t];  // beta*v - be*acc
            const float4* ar = (const float4*)(A_ + t * 16);   // At row t (zeros for u<=t)
            float4 a0 = ar[0], a1 = ar[1], a2 = ar[2], a3 = ar[3];
            acc[0]  += a0.x * berr[t];  acc[1]  += a0.y * berr[t];
            acc[2]  += a0.z * berr[t];  acc[3]  += a0.w * berr[t];
            acc[4]  += a1.x * berr[t];  acc[5]  += a1.y * berr[t];
            acc[6]  += a1.z * berr[t];  acc[7]  += a1.w * berr[t];
            acc[8]  += a2.x * berr[t];  acc[9]  += a2.y * berr[t];
            acc[10] += a2.z * berr[t];  acc[11] += a2.w * berr[t];
            acc[12] += a3.x * berr[t];  acc[13] += a3.y * berr[t];
            acc[14] += a3.z * berr[t];  acc[15] += a3.w * berr[t];
        }

        // ---- output o_{rb}[col] ----
        {
            float o = W_[16 + rb] * mydq;                       // Df_rb * dq_rb
            const float4* br = (const float4*)(B_ + rb * 20);   // zeros for s>rb
            float4 b0 = br[0], b1 = br[1], b2 = br[2], b3 = br[3];
            o += b0.x * berr[0]  + b0.y * berr[1]  + b0.z * berr[2]  + b0.w * berr[3];
            o += b1.x * berr[4]  + b1.y * berr[5]  + b1.z * berr[6]  + b1.w * berr[7];
            o += b2.x * berr[8]  + b2.y * berr[9]  + b2.z * berr[10] + b2.w * berr[11];
            o += b3.x * berr[12] + b3.y * berr[13] + b3.z * berr[14] + b3.w * berr[15];
            out[((size_t)(c * T + rb) * NH + h) * DV + col] = o;
        }

        // ---- state update: S = Df_15 * S + sum_s (C_s berr_s) k_s ----
        {
            float df = W_[16 + 15];
            u64 df2 = pk2(df, df);
            S2[0] = mul2(S2[0], df2);
            S2[1] = mul2(S2[1], df2);
            S2[2] = mul2(S2[2], df2);
            S2[3] = mul2(S2[3], df2);
            #pragma unroll
            for (int s = 0; s < T; s++) {
                float wv = W_[32 + s] * berr[s];
                u64 w2 = pk2(wv, wv);
                const float4* kp = (const float4*)(K_ + s * DK + rb * 8);
                float4 k0 = kp[0], k1 = kp[1];
                S2[0] = fma2(pk2(k0.x, k0.y), w2, S2[0]);
                S2[1] = fma2(pk2(k0.z, k0.w), w2, S2[1]);
                S2[2] = fma2(pk2(k1.x, k1.y), w2, S2[2]);
                S2[3] = fma2(pk2(k1.z, k1.w), w2, S2[3]);
            }
        }

        __syncthreads();                     // everyone done reading buf
        if (c + 2 < NC) {
            issue(c + 2, buf);
            asm volatile("cp.async.wait_group 1;" ::: "memory");
        } else {
            asm volatile("cp.async.wait_group 0;" ::: "memory");
        }
        __syncthreads();                     // new data visible to all
    }
}

extern "C" void kernel_launch(void* const* d_in, const int* in_sizes, int n_in,
                              void* d_out, int out_size)
{
    (void)in_sizes; (void)n_in; (void)out_size;
    const float* x      = (const float*)d_in[0];
    const float* agate  = (const float*)d_in[1];
    const float* bgate  = (const float*)d_in[2];
    const float* A_log  = (const float*)d_in[3];
    const float* dtbias = (const float*)d_in[4];
    const float* w      = (const float*)d_in[5];
    const float* cbias  = (const float*)d_in[6];

    prep_kernel<<<LSEQ, 256>>>(x, agate, bgate, A_log, dtbias, w, cbias);
    gram_kernel<<<NH * NC, 256>>>();
    scan_kernel<<<NH * 16, 128>>>((float*)d_out);
}